// round 6
// baseline (speedup 1.0000x reference)
#include <cuda_runtime.h>

#define DIMS 2048
#define SEQ  4096
#define SENT 2.0f            // tanh output in (-1,1), h0=0 -> never 2.0
#define NCTA 128
#define TB   128             // timesteps per producer block
#define NBLK (SEQ / TB)      // 32
#define RING 4               // ring slots (lookahead 512 steps)
#define RNN_T 256
#define PROD_T 64
#define THREADS (RNN_T + PROD_T)   // 320

// ---------------- scratch (static device globals; no allocation) ------------
__device__ __align__(16) float g_hist[(SEQ + 1) * DIMS];  // write-once h history
__device__ __align__(16) float g_Wt[DIMS * DIMS];         // W_hi^T per CTA: [c][k][r16]

// ---------------- asm helpers ------------------------------------------------
__device__ __forceinline__ float tanh_fast(float x) {
    float y; asm("tanh.approx.f32 %0, %1;" : "=f"(y) : "f"(x)); return y;
}
__device__ __forceinline__ float4 ldg_vol_v4(const float4* p) {
    float4 v;
    asm volatile("ld.volatile.global.v4.f32 {%0,%1,%2,%3}, [%4];"
                 : "=f"(v.x), "=f"(v.y), "=f"(v.z), "=f"(v.w) : "l"(p));
    return v;
}
__device__ __forceinline__ void stg_vol_v2(float2* p, float a, float b) {
    asm volatile("st.volatile.global.v2.f32 [%0], {%1,%2};"
                 :: "l"(p), "f"(a), "f"(b) : "memory");
}
__device__ __forceinline__ void ffma2(unsigned long long& d,
                                      unsigned long long a, unsigned long long b) {
    asm("fma.rn.f32x2 %0, %1, %2, %0;" : "+l"(d) : "l"(a), "l"(b));
}
__device__ __forceinline__ unsigned long long add2(unsigned long long a,
                                                   unsigned long long b) {
    unsigned long long s;
    asm("add.rn.f32x2 %0, %1, %2;" : "=l"(s) : "l"(a), "l"(b));
    return s;
}
__device__ __forceinline__ unsigned long long pack2(float x) {
    unsigned long long r; asm("mov.b64 %0, {%1, %1};" : "=l"(r) : "f"(x)); return r;
}
__device__ __forceinline__ float f32x2_hsum(unsigned long long a, unsigned long long b) {
    unsigned long long s = add2(a, b);
    float2 f = *reinterpret_cast<float2*>(&s);
    return f.x + f.y;
}
__device__ __forceinline__ float2 lds_vol_f2(const float2* p) {
    float2 v;
    asm volatile("ld.volatile.v2.f32 {%0,%1}, [%2];" : "=f"(v.x), "=f"(v.y) : "l"(p));
    return v;
}
__device__ __forceinline__ void bar_rnn()  { asm volatile("bar.sync 0, 256;" ::: "memory"); }
__device__ __forceinline__ void bar_prod() { asm volatile("bar.sync 1, 64;"  ::: "memory"); }

// ---------------- init kernels ------------------------------------------------
__global__ void poison_kernel() {
    const float4 s = make_float4(SENT, SENT, SENT, SENT);
    float4* p = (float4*)g_hist;
    const int total = (SEQ + 1) * (DIMS / 4);
    for (int w = blockIdx.x * blockDim.x + threadIdx.x; w < total;
         w += gridDim.x * blockDim.x)
        p[w] = s;
}
__global__ void seed_kernel(const float* __restrict__ h0) {
    int i = blockIdx.x * blockDim.x + threadIdx.x;
    if (i < DIMS) g_hist[i] = h0[i];
}
// g_Wt[((c*2048 + k)*16) + r] = W_hi[(16c + r)*2048 + k]
__global__ void transpose_kernel(const float* __restrict__ W_hi) {
    int idx = blockIdx.x * blockDim.x + threadIdx.x;   // 0 .. DIMS*DIMS-1
    int r = idx & 15;
    int k = (idx >> 4) & (DIMS - 1);
    int c = idx >> 15;
    g_Wt[idx] = W_hi[(size_t)((c << 4) + r) * DIMS + k];
}

// ---------------- fused persistent kernel --------------------------------------
// 128 CTAs x 320 threads, 1 CTA/SM.
//   warps 0-7  (tid<256): sequential RNN scan (value-signaled h exchange).
//   warps 8-9  (tid>=256): producers — compute A = X@W_hi^T + b for this CTA's
//                          16 rows, 128 timesteps per block, into a 4-slot
//                          smem ring. CTA-local sync via volatile smem counters.
__global__ __launch_bounds__(THREADS, 1) void rnn_kernel(
    const float* __restrict__ X, const float* __restrict__ Whh,
    const float* __restrict__ b, float* __restrict__ out)
{
    __shared__ __align__(16) float4 h_s[DIMS / 4];          // 8 KB
    __shared__ __align__(16) float  A_ring[RING * TB * 16]; // 32 KB
    __shared__ __align__(16) float  b_s[16];
    __shared__ volatile int s_prod_done;   // blocks produced
    __shared__ volatile int s_rnn_done;    // steps consumed

    const int tid = threadIdx.x;
    const int cta = blockIdx.x;

    if (tid == 0) { s_prod_done = 0; s_rnn_done = 0; }
    if (tid < 16) b_s[tid] = b[cta * 16 + tid];

    // RNN warps stage their W_hh rows into registers.
    const int wid  = tid >> 5;
    const int lane = tid & 31;
    const int row0 = cta * 16 + wid * 2;
    const int row1 = row0 + 1;
    ulonglong2 w0[16], w1[16];
    if (tid < RNN_T) {
        const ulonglong2* W0 = (const ulonglong2*)(Whh + (size_t)row0 * DIMS);
        const ulonglong2* W1 = (const ulonglong2*)(Whh + (size_t)row1 * DIMS);
#pragma unroll
        for (int k = 0; k < 16; k++) { w0[k] = W0[lane + 32 * k]; w1[k] = W1[lane + 32 * k]; }
    }
    __syncthreads();   // all 320: init visible, roles may diverge now

    if (tid < RNN_T) {
        // =================== RNN role (warps 0-7) ===================
        for (int t = 0; t < SEQ; t++) {
            const float4* hb = (const float4*)(g_hist + (size_t)t * DIMS);

            // lane0: A operands from the smem ring (+ residual x), off h-chain.
            float a0 = 0.f, a1 = 0.f, xr0 = 0.f, xr1 = 0.f;
            if (lane == 0) {
                const int blk = t >> 7;
                while (s_prod_done <= blk) { }          // rare after warmup
                asm volatile("" ::: "memory");
                const float2* ap = (const float2*)
                    (A_ring + ((blk & (RING - 1)) * TB + (t & (TB - 1))) * 16);
                float2 av = lds_vol_f2(ap + wid);
                a0 = av.x; a1 = av.y;
                xr0 = X[(size_t)t * DIMS + row0];
                xr1 = X[(size_t)t * DIMS + row1];
            }

            // Ingest h_prev: payload IS the signal (sentinel-poison, write-once).
            {
                float4 va = ldg_vol_v4(hb + tid);
                float4 vb = ldg_vol_v4(hb + tid + RNN_T);
                while (va.x == SENT || va.y == SENT || va.z == SENT || va.w == SENT)
                    va = ldg_vol_v4(hb + tid);
                while (vb.x == SENT || vb.y == SENT || vb.z == SENT || vb.w == SENT)
                    vb = ldg_vol_v4(hb + tid + RNN_T);
                h_s[tid]         = va;
                h_s[tid + RNN_T] = vb;
            }
            bar_rnn();   // h_s staged

            // 2 dot products per warp; W in registers, packed f32x2 FMA.
            unsigned long long a0x = 0ull, a0y = 0ull, a1x = 0ull, a1y = 0ull;
#pragma unroll
            for (int k = 0; k < 16; k++) {
                ulonglong2 hv = *(const ulonglong2*)&h_s[lane + 32 * k];
                ffma2(a0x, w0[k].x, hv.x);  ffma2(a0y, w0[k].y, hv.y);
                ffma2(a1x, w1[k].x, hv.x);  ffma2(a1y, w1[k].y, hv.y);
            }
            float acc0 = f32x2_hsum(a0x, a0y);
            float acc1 = f32x2_hsum(a1x, a1y);
#pragma unroll
            for (int o = 16; o > 0; o >>= 1) {
                acc0 += __shfl_xor_sync(0xffffffffu, acc0, o);
                acc1 += __shfl_xor_sync(0xffffffffu, acc1, o);
            }

            if (lane == 0) {
                float h0n = tanh_fast(a0 + acc0);
                float h1n = tanh_fast(a1 + acc1);
                // publish first (write-once v2 word; single publisher, volatile)
                stg_vol_v2((float2*)(g_hist + (size_t)(t + 1) * DIMS + row0), h0n, h1n);
                out[(size_t)t * DIMS + row0] = xr0 + h0n;   // residual, off-chain
                out[(size_t)t * DIMS + row1] = xr1 + h1n;
            }
            bar_rnn();   // all h_s & ring reads of step t done
            if (tid == 0) s_rnn_done = t + 1;
        }
    } else {
        // =================== producer role (warps 8-9) ===================
        const int j = tid - RNN_T;     // 0..63 : owns timesteps t0+j and t0+j+64
        const ulonglong2* wbase =
            (const ulonglong2*)(g_Wt + (size_t)cta * (DIMS * 16));
        unsigned long long b2[8];
#pragma unroll
        for (int rp = 0; rp < 8; rp++) b2[rp] = ((const unsigned long long*)b_s)[rp];

        for (int B = 0; B < NBLK; B++) {
            // flow control: don't overwrite a slot still being consumed
            if (B >= RING) {
                const int need = TB * (B - (RING - 1));
                while (s_rnn_done < need) { }
                asm volatile("" ::: "memory");
            }
            const int t0 = B * TB;
            const float4* Xa = (const float4*)(X + (size_t)(t0 + j) * DIMS);
            const float4* Xb = (const float4*)(X + (size_t)(t0 + j + 64) * DIMS);

            unsigned long long accA[8], accB[8];
#pragma unroll
            for (int rp = 0; rp < 8; rp++) { accA[rp] = 0ull; accB[rp] = 0ull; }

            float4 xa0 = __ldcs(Xa + 0), xa1 = __ldcs(Xa + 1);
            float4 xb0 = __ldcs(Xb + 0), xb1 = __ldcs(Xb + 1);
#pragma unroll 1
            for (int kk = 0; kk < DIMS / 8; kk++) {          // 8 k per iter
                const int nk = (kk + 1) & (DIMS / 8 - 1);    // wraps on last (dummy)
                float4 na0 = __ldcs(Xa + 2 * nk),     na1 = __ldcs(Xa + 2 * nk + 1);
                float4 nb0 = __ldcs(Xb + 2 * nk),     nb1 = __ldcs(Xb + 2 * nk + 1);
                float xs1[8], xs2[8];
                *(float4*)&xs1[0] = xa0; *(float4*)&xs1[4] = xa1;
                *(float4*)&xs2[0] = xb0; *(float4*)&xs2[4] = xb1;
                const ulonglong2* wp = wbase + (size_t)kk * 32;  // 8k x 4 ull2
#pragma unroll
                for (int i = 0; i < 8; i++) {
                    ulonglong2 wa = wp[i * 4 + 0], wb = wp[i * 4 + 1];
                    ulonglong2 wc = wp[i * 4 + 2], wd = wp[i * 4 + 3];
                    unsigned long long x1 = pack2(xs1[i]);
                    unsigned long long x2 = pack2(xs2[i]);
                    ffma2(accA[0], wa.x, x1); ffma2(accA[1], wa.y, x1);
                    ffma2(accA[2], wb.x, x1); ffma2(accA[3], wb.y, x1);
                    ffma2(accA[4], wc.x, x1); ffma2(accA[5], wc.y, x1);
                    ffma2(accA[6], wd.x, x1); ffma2(accA[7], wd.y, x1);
                    ffma2(accB[0], wa.x, x2); ffma2(accB[1], wa.y, x2);
                    ffma2(accB[2], wb.x, x2); ffma2(accB[3], wb.y, x2);
                    ffma2(accB[4], wc.x, x2); ffma2(accB[5], wc.y, x2);
                    ffma2(accB[6], wd.x, x2); ffma2(accB[7], wd.y, x2);
                }
                xa0 = na0; xa1 = na1; xb0 = nb0; xb1 = nb1;
            }

            // write block to ring (+ bias)
            const int slot = B & (RING - 1);
            unsigned long long* d1 =
                (unsigned long long*)(A_ring + (slot * TB + j) * 16);
            unsigned long long* d2 =
                (unsigned long long*)(A_ring + (slot * TB + j + 64) * 16);
#pragma unroll
            for (int rp = 0; rp < 8; rp++) {
                d1[rp] = add2(accA[rp], b2[rp]);
                d2[rp] = add2(accB[rp], b2[rp]);
            }
            bar_prod();                       // both producer warps done (STS drained)
            if (j == 0) s_prod_done = B + 1;  // volatile flag after drain
        }
    }
}

// ---------------- launch ---------------------------------------------------------
extern "C" void kernel_launch(void* const* d_in, const int* in_sizes, int n_in,
                              void* d_out, int out_size) {
    const float* X    = (const float*)d_in[0];  // [SEQ, DIMS]
    const float* W_hi = (const float*)d_in[1];  // [DIMS, DIMS]
    const float* W_hh = (const float*)d_in[2];  // [DIMS, DIMS]
    const float* b    = (const float*)d_in[3];  // [DIMS]
    const float* h0   = (const float*)d_in[4];  // [DIMS]
    float* out = (float*)d_out;

    poison_kernel<<<1024, 256>>>();
    seed_kernel<<<(DIMS + 255) / 256, 256>>>(h0);
    transpose_kernel<<<(DIMS * DIMS) / 256, 256>>>(W_hi);

    rnn_kernel<<<NCTA, THREADS>>>(X, W_hh, b, out);
}